// round 9
// baseline (speedup 1.0000x reference)
#include <cuda_runtime.h>
#include <cuda_bf16.h>
#include <math.h>

#define NB 4
#define NM 32
#define CT 282
#define CTP 284             // padded row stride for d_At (float4-safe tail)
#define CT2 (CT*CT)
#define KTOT 24576          // 2 * 12288 floats per Gram row
#define SEG 256
#define NSEG 96
#define EPSR 1e-3f

#define SXP_N 16008         // X-pyramid complex elements per (b,m)
#define SC_N  3720          // C-table complex elements per (b,m)
#define SMEM_MAIN ((SXP_N + SC_N) * 8 + 1364 * 4)   // 163280 bytes

// per-level constants
__constant__ int c_h[5]     = {2,4,8,16,32};
__constant__ int c_cnt[5]   = {192,48,24,12,6};
__constant__ int c_cbase[6] = {0,192,240,264,276,282};
__constant__ int c_OffC[5]  = {0,768,1536,3072,6144};   // complex offset of level block in Zh
__constant__ int c_LB[5]    = {0,768,1728,3744,7824};   // pyramid base per level
__constant__ int c_PS[5]    = {4,20,84,340,1364};       // pyramid size per channel of level
__constant__ int c_LO[5]    = {0,4,20,84,340};          // offset of level-l slice inside a pyramid
__constant__ int c_Cb[4]    = {0,360,1032,2184};        // C-table base per source level

// dft job table: 42 jobs
__constant__ int jb_l[42]  = {0,0,0,0,0,0, 1,1,1,1,1,1, 2,2,2,2,2,2,2,2,2,2,2,2,
                              3,3,3,3,3,3,3,3,3,3,3,3, 4,4,4,4,4,4};
__constant__ int jb_c0[42] = {0,32,64,96,128,160, 0,8,16,24,32,40,
                              0,2,4,6,8,10,12,14,16,18,20,22,
                              0,1,2,3,4,5,6,7,8,9,10,11, 0,1,2,3,4,5};
__constant__ int jb_n[42]  = {32,32,32,32,32,32, 8,8,8,8,8,8, 2,2,2,2,2,2,2,2,2,2,2,2,
                              1,1,1,1,1,1,1,1,1,1,1,1, 1,1,1,1,1,1};

// scratch (device globals; no allocation)
__device__ float  d_A [NM*CT2];                        // A[m][d][c] = L[m,c,d]-L[m,d,c]
__device__ __align__(16) float d_At[NM*CT*CTP];        // At[m][c][d] (stride CTP)
__device__ float  d_Spyr[NM*1364];                     // alias pyramid of s per mode
__device__ __align__(16) float2 d_Zh[NB*12288];        // per-level DFTs of z
__device__ __align__(16) float  d_V [(size_t)NB*33*KTOT]; // Gram rows (0..31 = U-hat, 32 = w-hat)
__device__ float  d_G [NB*1089];                       // Gram accumulators (atomic)

struct InPtrs { const float* z[5]; const float* w[5]; };

// ---------------------------------------------------------------- A = L^T - L (+transpose)
__global__ void k_prepA(const float* __restrict__ L){
    __shared__ float Ta[32][33];
    __shared__ float Tv[32][33];
    int m  = blockIdx.z;
    int c0 = blockIdx.x*32, d0 = blockIdx.y*32;
    int tx = threadIdx.x, ty = threadIdx.y;
    const float* Lm = L + (size_t)m*CT2;
    int ci = c0+ty, dj = d0+tx;
    Ta[ty][tx] = (ci<CT && dj<CT) ? Lm[ci*CT + dj] : 0.f;
    __syncthreads();
    int di = d0+ty, cj = c0+tx;
    float v = 0.f;
    if (di<CT && cj<CT){
        v = Ta[tx][ty] - Lm[di*CT + cj];
        d_A[((size_t)m*CT + di)*CT + cj] = v;
    }
    Tv[ty][tx] = v;
    __syncthreads();
    int ci2 = c0+ty, dj2 = d0+tx;
    if (ci2<CT && dj2<CT)
        d_At[((size_t)m*CT + ci2)*CTP + dj2] = Tv[tx][ty];
}

// ------------------------------------------------------- s pyramid + zero d_G
__global__ void k_spyr(const float* __restrict__ lam){
    __shared__ float sA[1024];
    __shared__ float sB[256];
    int m = blockIdx.x;
    int tid = threadIdx.x;          // 256
    int gidx = m*256 + tid;
    if (gidx < NB*1089) d_G[gidx] = 0.f;
    const float* lm = lam + m*1024;
    for (int t=tid; t<1024; t+=256){
        int p = t>>5, q = t&31;
        float v = lm[t] - lm[(((32-p)&31)<<5) + ((32-q)&31)];
        sA[t] = v;
        d_Spyr[m*1364 + 340 + t] = v;
    }
    float* src = sA; float* dst = sB;
    int hs = 32;
    for (int k=0; k<4; ++k){
        __syncthreads();
        int hn = hs>>1;
        int off = c_LO[3-k];        // 84,20,4,0
        for (int t=tid; t<hn*hn; t+=256){
            int p = t/hn, q = t-p*hn;
            float v = src[p*hs+q] + src[(p+hn)*hs+q]
                    + src[p*hs+q+hn] + src[(p+hn)*hs+q+hn];
            dst[t] = v;
            d_Spyr[m*1364 + off + t] = v;
        }
        float* tmp = src; src = dst; dst = tmp;
        hs = hn;
    }
}

// ----------------------- batched small 2D DFTs of z (and w -> V row 32)
__global__ void __launch_bounds__(256) k_dft(InPtrs P){
    __shared__ float sIn[1024];
    __shared__ float tRe[1024];
    __shared__ float tIm[1024];
    __shared__ float2 tw[32];
    int j = blockIdx.x, b = blockIdx.y, isw = blockIdx.z;
    int l = jb_l[j];
    int h = c_h[l], hm = h-1;
    int lh = 31 - __clz(h);
    int lh2 = 2*lh;
    int h2 = h*h;
    int c0 = jb_c0[j], nch = jb_n[j];
    int npts = nch*h2;
    const float* in = (isw ? P.w[l] : P.z[l]) + (size_t)(b*c_cnt[l] + c0)*h2;
    int tid = threadIdx.x;
    if (tid < h){
        float sn, cn; __sincosf(-6.283185307179586f*(float)tid/(float)h, &sn, &cn);
        tw[tid] = make_float2(cn, sn);
    }
    for (int t=tid; t<npts; t+=256) sIn[t] = in[t];
    __syncthreads();
    for (int t=tid; t<npts; t+=256){
        int ch = t>>lh2;
        int pt = t & (h2-1);
        int p = pt>>lh, x = pt&hm;
        const float* base = sIn + (ch<<lh2) + x;
        float ar=0.f, ai=0.f;
        for (int y=0; y<h; ++y){
            float2 e = tw[(p*y)&hm];
            float v = base[y<<lh];
            ar += v*e.x; ai += v*e.y;
        }
        tRe[t]=ar; tIm[t]=ai;
    }
    __syncthreads();
    float inv = 1.0f/(float)h;
    float* vrow = d_V + ((size_t)(b*33+32))*KTOT;
    for (int t=tid; t<npts; t+=256){
        int ch = t>>lh2;
        int pt = t & (h2-1);
        int p = pt>>lh, q = pt&hm;
        const float* bR = tRe + (ch<<lh2) + (p<<lh);
        const float* bI = tIm + (ch<<lh2) + (p<<lh);
        float ar=0.f, ai=0.f;
        for (int x=0; x<h; ++x){
            float2 e = tw[(q*x)&hm];
            float re = bR[x], im = bI[x];
            ar += re*e.x - im*e.y;
            ai += re*e.y + im*e.x;
        }
        int kk = c_OffC[l] + (c0<<lh2) + t;
        if (!isw){
            d_Zh[b*12288 + kk] = make_float2(ar, ai);
        } else {
            vrow[2*kk  ] =  ai*inv;
            vrow[2*kk+1] = -ar*inv;
        }
    }
}

// ---------------- 4d x 4k fine accumulation over source levels lc >= l only
// (coarse sources lc < l are handled by the C table; their pyramids have no
//  level-l slice, so touching them here was R8's correctness bug)
__device__ __forceinline__ void fine_acc4(const float2* __restrict__ sXp,
                                          const float* __restrict__ At4,
                                          int l, int k0, float* ac){
    for (int lc=l; lc<5; ++lc){
        int ps = c_PS[lc];
        const float2* xp = sXp + c_LB[lc] + c_LO[l] + k0;
        int cb = c_cbase[lc], ce = c_cbase[lc+1];
        const float* ap = At4 + (size_t)cb*CTP;
        for (int c=cb; c<ce; ++c){
            float4 a = __ldg((const float4*)ap);
            float4 x01 = *(const float4*)(xp);
            float4 x23 = *(const float4*)(xp+2);
            ac[0] += a.x*x01.x; ac[1] += a.x*x01.y;
            ac[2] += a.x*x01.z; ac[3] += a.x*x01.w;
            ac[4] += a.x*x23.x; ac[5] += a.x*x23.y;
            ac[6] += a.x*x23.z; ac[7] += a.x*x23.w;
            ac[8] += a.y*x01.x; ac[9] += a.y*x01.y;
            ac[10]+= a.y*x01.z; ac[11]+= a.y*x01.w;
            ac[12]+= a.y*x23.x; ac[13]+= a.y*x23.y;
            ac[14]+= a.y*x23.z; ac[15]+= a.y*x23.w;
            ac[16]+= a.z*x01.x; ac[17]+= a.z*x01.y;
            ac[18]+= a.z*x01.z; ac[19]+= a.z*x01.w;
            ac[20]+= a.z*x23.x; ac[21]+= a.z*x23.y;
            ac[22]+= a.z*x23.z; ac[23]+= a.z*x23.w;
            ac[24]+= a.w*x01.x; ac[25]+= a.w*x01.y;
            ac[26]+= a.w*x01.z; ac[27]+= a.w*x01.w;
            ac[28]+= a.w*x23.x; ac[29]+= a.w*x23.y;
            ac[30]+= a.w*x23.z; ac[31]+= a.w*x23.w;
            xp += ps;
            ap += CTP;
        }
    }
}

// ====================== fused per-(b,m) vector-field kernel ======================
__global__ void __launch_bounds__(512) k_main(){
    extern __shared__ float smraw[];
    float2* sXp = (float2*)smraw;              // [SXP_N]
    float2* sC  = sXp + SXP_N;                 // [SC_N]
    float*  sS  = (float*)(sC + SC_N);         // [1364]
    int m = blockIdx.x, b = blockIdx.y;
    int tid = threadIdx.x;

    for (int t=tid; t<1364; t+=512) sS[t] = d_Spyr[m*1364 + t];
    for (int t=tid; t<720;  t+=512) ((float*)sC)[t] = 0.f;   // ls=0 C region (atomic)
    __syncthreads();

    const float2* Zb = d_Zh + b*12288;

    // ---- phase 1a: finest slices  sXp = S (x) Zh
    for (int f=tid; f<12288; f+=512){
        int l, rel;
        if (f<768){l=0;rel=f;} else if (f<1536){l=1;rel=f-768;}
        else if (f<3072){l=2;rel=f-1536;} else if (f<6144){l=3;rel=f-3072;}
        else {l=4;rel=f-6144;}
        int h2 = c_h[l]*c_h[l];
        int dl = rel/h2, pt = rel-dl*h2;
        float s = sS[c_LO[l]+pt];
        float2 z = Zb[f];
        sXp[c_LB[l] + c_PS[l]*dl + c_LO[l] + pt] = make_float2(s*z.x, s*z.y);
    }
    __syncthreads();

    // ---- phase 1b: alias pyramid, 4 steps
    for (int step=1; step<=4; ++step){
        for (int lc=step; lc<=4; ++lc){
            int lt = lc-step;
            int hn = c_h[lt], hsrc = hn*2, hh = hn*hn;
            int n = c_cnt[lc]*hh;
            for (int t=tid; t<n; t+=512){
                int dl = t/hh, pt = t-dl*hh;
                int p = pt/hn, q = pt-p*hn;
                float2* bch = sXp + c_LB[lc] + c_PS[lc]*dl;
                const float2* src = bch + c_LO[lt+1];
                float2 a0=src[p*hsrc+q],    a1=src[(p+hn)*hsrc+q];
                float2 a2=src[p*hsrc+q+hn], a3=src[(p+hn)*hsrc+q+hn];
                bch[c_LO[lt]+pt] = make_float2(a0.x+a1.x+a2.x+a3.x, a0.y+a1.y+a2.y+a3.y);
            }
        }
        __syncthreads();
    }

    // ---- phase 2: coarse residue table  C[ls][di][r] = sum_c A[d,c] Zh_c[r]
    for (int it=tid; it<1110; it+=512){
        int ls, di, r0, clo, chi, hh;
        float2* Cp; bool atom;
        if (it < 270){
            ls=0; di=it/3; int chunk=it-3*di;
            r0=0; clo=chunk*64; chi=clo+64; hh=4;
            Cp = sC + di*4; atom=true;
        } else if (it < 438){
            ls=1; int t2=it-270; di=t2>>2; int rt=t2&3; r0=rt*4;
            clo=0; chi=48; hh=16; Cp = sC + 360 + di*16 + r0; atom=false;
        } else if (it < 726){
            ls=2; int t2=it-438; di=t2>>4; int rt=t2&15; r0=rt*4;
            clo=0; chi=24; hh=64; Cp = sC + 1032 + di*64 + r0; atom=false;
        } else {
            ls=3; int t2=it-726; di=t2>>6; int rt=t2&63; r0=rt*4;
            clo=0; chi=12; hh=256; Cp = sC + 2184 + di*256 + r0; atom=false;
        }
        int dg = c_cbase[ls+1] + di;
        const float* Ar = d_A + ((size_t)m*CT + dg)*CT + c_cbase[ls];
        const float2* Zp = Zb + c_OffC[ls] + clo*hh + r0;
        float xr0=0,xi0=0,xr1=0,xi1=0,xr2=0,xi2=0,xr3=0,xi3=0;
        for (int c=clo; c<chi; ++c){
            float a = __ldg(Ar + c);
            float4 z01 = __ldg((const float4*)(Zp));
            float4 z23 = __ldg((const float4*)(Zp+2));
            xr0 += a*z01.x; xi0 += a*z01.y;
            xr1 += a*z01.z; xi1 += a*z01.w;
            xr2 += a*z23.x; xi2 += a*z23.y;
            xr3 += a*z23.z; xi3 += a*z23.w;
            Zp += hh;
        }
        if (atom){
            float* f = (float*)Cp;
            atomicAdd(f+0, xr0); atomicAdd(f+1, xi0);
            atomicAdd(f+2, xr1); atomicAdd(f+3, xi1);
            atomicAdd(f+4, xr2); atomicAdd(f+5, xi2);
            atomicAdd(f+6, xr3); atomicAdd(f+7, xi3);
        } else {
            Cp[0]=make_float2(xr0,xi0); Cp[1]=make_float2(xr1,xi1);
            Cp[2]=make_float2(xr2,xi2); Cp[3]=make_float2(xr3,xi3);
        }
    }
    __syncthreads();

    // ---- phase 3: mixing, 4d x 4k items, 282 channel-iterations each.
    // [0,48)    l0: 48 dgroups, k0=0
    // [48,96)   l1: 12 dg x 4 kt
    // [96,192)  l2: 6 dg x 16 kt
    // [192,384) l3: 3 dg x 64 kt
    // [384,896) l4: 2 dg x 256 kt   (dg=1 has only 2 valid d)
    float* vbase = d_V + ((size_t)(b*33+m))*KTOT;
    const float* Atm = d_At + (size_t)m*CT*CTP;
    for (int it=tid; it<896; it+=512){
        float ac[32];
        #pragma unroll
        for (int j=0;j<32;++j) ac[j]=0.f;

        int l, dg, kt;
        if (it < 48){ l=0; dg=it; kt=0; }
        else if (it < 96){ int t2=it-48; l=1; dg=t2>>2; kt=t2&3; }
        else if (it < 192){ int t2=it-96; l=2; dg=t2>>4; kt=t2&15; }
        else if (it < 384){ int t2=it-192; l=3; dg=t2>>6; kt=t2&63; }
        else { int t2=it-384; l=4; dg=t2>>8; kt=t2&255; }

        int h=c_h[l], h2=h*h, hm=h-1;
        int lh = 31 - __clz(h);
        int k0 = kt*4;
        int d0 = c_cbase[l] + 4*dg;
        int dcnt = c_cbase[l+1] - d0; if (dcnt > 4) dcnt = 4;

        if (l > 0){
            int pp[4], qq[4];
            #pragma unroll
            for (int j=0;j<4;++j){ int k=k0+j; pp[j]=k>>lh; qq[j]=k&hm; }
            for (int ls=0; ls<l; ++ls){
                int hs=c_h[ls], hh=hs*hs, hsm=hs-1;
                const float2* Cp = sC + c_Cb[ls] + (d0 - c_cbase[ls+1])*hh;
                int djmax = dcnt;
                #pragma unroll
                for (int j=0;j<4;++j){
                    int r = (pp[j]&hsm)*hs + (qq[j]&hsm);
                    for (int dj=0; dj<djmax; ++dj){
                        float2 v = Cp[dj*hh + r];
                        ac[8*dj+2*j]   += v.x;
                        ac[8*dj+2*j+1] += v.y;
                    }
                }
            }
            const float* Sl = sS + c_LO[l] + k0;
            #pragma unroll
            for (int j=0;j<4;++j){
                float s = Sl[j];
                #pragma unroll
                for (int dj=0; dj<4; ++dj){
                    ac[8*dj+2*j]   *= s;
                    ac[8*dj+2*j+1] *= s;
                }
            }
        }

        fine_acc4(sXp, Atm + d0, l, k0, ac);

        float scale = (float)h * (1.0f/1024.0f);
        #pragma unroll
        for (int dj=0; dj<4; ++dj){
            if (dj < dcnt){
                float* vp = vbase + 2*(c_OffC[l] + (d0 - c_cbase[l] + dj)*h2 + k0);
                float4 o0, o1;
                o0.x = scale*ac[8*dj+0]; o0.y = scale*ac[8*dj+1];
                o0.z = scale*ac[8*dj+2]; o0.w = scale*ac[8*dj+3];
                o1.x = scale*ac[8*dj+4]; o1.y = scale*ac[8*dj+5];
                o1.z = scale*ac[8*dj+6]; o1.w = scale*ac[8*dj+7];
                *(float4*)(vp)   = o0;
                *(float4*)(vp+4) = o1;
            }
        }
    }
}

// ------------------------------------------------- segmented 33x33 Gram -> atomic d_G
__global__ void __launch_bounds__(256) k_gram(){
    __shared__ float sm[34*257];
    int seg = blockIdx.x, b = blockIdx.y;
    int tid = threadIdx.x;          // 256
    const float* Vb = d_V + (size_t)b*33*KTOT + seg*SEG;
    for (int r=0; r<33; ++r) sm[r*257+tid] = Vb[(size_t)r*KTOT + tid];
    sm[33*257+tid] = 0.f;
    __syncthreads();
    float* gG = d_G + b*1089;
    if (tid < 153){
        int t = tid;
        int ti = (int)((35.0f - sqrtf(1225.0f - 8.0f*(float)t)) * 0.5f);
        if (ti > 16) ti = 16; if (ti < 0) ti = 0;
        int off = 17*ti - (ti*(ti-1))/2;
        while (off > t){ ti--; off = 17*ti - (ti*(ti-1))/2; }
        while (off + (17-ti) <= t){ off += 17-ti; ti++; }
        int tj = ti + (t - off);
        const float* r0 = sm + (2*ti)*257;
        const float* r1 = r0 + 257;
        const float* q0 = sm + (2*tj)*257;
        const float* q1 = q0 + 257;
        float a00=0,a01=0,a10=0,a11=0;
        #pragma unroll 4
        for (int k=0; k<SEG; ++k){
            float x0=r0[k], x1=r1[k], y0=q0[k], y1=q1[k];
            a00 += x0*y0; a01 += x0*y1;
            a10 += x1*y0; a11 += x1*y1;
        }
        int i0=2*ti, j0=2*tj;
        int i1=i0+1, j1=j0+1;
        atomicAdd(gG + i0*33+j0, a00);
        if (j1<33) atomicAdd(gG + i0*33+j1, a01);
        if (i1<33) atomicAdd(gG + i1*33+j0, a10);
        if (i1<33 && j1<33) atomicAdd(gG + i1*33+j1, a11);
        if (ti != tj){
            atomicAdd(gG + j0*33+i0, a00);
            if (j1<33) atomicAdd(gG + j1*33+i0, a01);
            if (i1<33) atomicAdd(gG + j0*33+i1, a10);
            if (i1<33 && j1<33) atomicAdd(gG + j1*33+i1, a11);
        }
    }
}

// ------------------------------------------------- stats + Cholesky + logdet
__global__ void k_final(float* __restrict__ out){
    __shared__ float G[1089];
    __shared__ float Mch[32][33];
    __shared__ float sc0;
    int b = blockIdx.x;
    int tid = threadIdx.x;          // 256
    for (int pair=tid; pair<1089; pair+=256) G[pair] = d_G[b*1089 + pair];
    __syncthreads();
    if (tid < 32){
        float dg = G[tid*33+tid];
        for (int o=16;o>0;o>>=1) dg += __shfl_down_sync(0xffffffffu, dg, o);
        if (tid==0){
            float var = dg * (1.0f/32.0f);
            if (var < 1e-6f) var = 1e-6f;
            sc0 = var;
        }
    }
    __syncthreads();
    float var = sc0;
    float inv_var = 1.0f/var;
    for (int t=tid; t<1024; t+=256){
        int i = t>>5, j = t&31;
        Mch[i][j] = G[i*33+j]*inv_var + ((i==j)?EPSR:0.f);
    }
    __syncthreads();
    for (int k=0; k<32; ++k){
        if (tid==0) Mch[k][k] = sqrtf(Mch[k][k]);
        __syncthreads();
        if (tid>k && tid<32) Mch[tid][k] /= Mch[k][k];
        __syncthreads();
        if (tid>k && tid<32){
            float lik = Mch[tid][k];
            for (int j=k+1; j<=tid; ++j) Mch[tid][j] -= lik*Mch[j][k];
        }
        __syncthreads();
    }
    if (tid < 32){
        float ld  = 2.0f*logf(Mch[tid][tid]);
        float zw  = G[tid*33+32];
        float zw2 = zw*zw;
        for (int o=16;o>0;o>>=1){
            ld  += __shfl_down_sync(0xffffffffu, ld,  o);
            zw2 += __shfl_down_sync(0xffffffffu, zw2, o);
        }
        if (tid==0){
            float trace = EPSR*G[32*33+32] + zw2*inv_var;
            out[b] = 0.5f*(ld - trace);
        }
    }
}

// ----------------------------------------------------------------------------
extern "C" void kernel_launch(void* const* d_in, const int* in_sizes, int n_in,
                              void* d_out, int out_size){
    (void)n_in; (void)out_size;
    InPtrs P;
    const float* L; const float* lam;
    if (in_sizes[0] > 1000000){
        // alphabetical: L, lam, w0..w4, z0..z4
        L   = (const float*)d_in[0];
        lam = (const float*)d_in[1];
        for (int l=0;l<5;++l){ P.w[l] = (const float*)d_in[2+l]; P.z[l] = (const float*)d_in[7+l]; }
    } else if (in_sizes[2] == 6144){
        // grouped: z0..z4, w0..w4, L, lam
        for (int l=0;l<5;++l){ P.z[l] = (const float*)d_in[l]; P.w[l] = (const float*)d_in[5+l]; }
        L   = (const float*)d_in[10];
        lam = (const float*)d_in[11];
    } else {
        // dict insertion order: z0,w0,z1,w1,...,L,lam
        for (int l=0;l<5;++l){ P.z[l] = (const float*)d_in[2*l]; P.w[l] = (const float*)d_in[2*l+1]; }
        L   = (const float*)d_in[10];
        lam = (const float*)d_in[11];
    }
    float* out = (float*)d_out;

    static int smem_set = 0;
    if (!smem_set){
        cudaFuncSetAttribute(k_main, cudaFuncAttributeMaxDynamicSharedMemorySize, SMEM_MAIN);
        smem_set = 1;
    }

    dim3 tA(32,32), gA(9,9,NM);
    k_prepA<<<gA, tA>>>(L);
    k_spyr<<<NM, 256>>>(lam);
    k_dft<<<dim3(42, NB, 2), 256>>>(P);
    k_main<<<dim3(NM, NB), 512, SMEM_MAIN>>>();
    k_gram<<<dim3(NSEG, NB), 256>>>();
    k_final<<<NB, 256>>>(out);
}

// round 10
// speedup vs baseline: 1.0450x; 1.0450x over previous
#include <cuda_runtime.h>
#include <cuda_bf16.h>
#include <math.h>

#define NB 4
#define NM 32
#define CT 282
#define CTP 284             // padded row stride for d_At (float4-safe tail)
#define CT2 (CT*CT)
#define KTOT 24576          // 2 * 12288 floats per Gram row
#define SEG 256
#define NSEG 96
#define EPSR 1e-3f

#define SXP_N 16008         // X-pyramid complex elements per (b,m)
#define SC_N  3720          // C-table complex elements per (b,m)
// sXp + sC (float2) + sS (1364 f) + sU (3072 f)
#define SMEM_MAIN ((SXP_N + SC_N) * 8 + (1364 + 3072) * 4)   // 175568 bytes

// per-level constants
__constant__ int c_h[5]     = {2,4,8,16,32};
__constant__ int c_cnt[5]   = {192,48,24,12,6};
__constant__ int c_cbase[6] = {0,192,240,264,276,282};
__constant__ int c_OffC[5]  = {0,768,1536,3072,6144};   // complex offset of level block in Zh
__constant__ int c_LB[5]    = {0,768,1728,3744,7824};   // pyramid base per level
__constant__ int c_PS[5]    = {4,20,84,340,1364};       // pyramid size per channel of level
__constant__ int c_LO[5]    = {0,4,20,84,340};          // offset of level-l slice inside a pyramid
__constant__ int c_Cb[4]    = {0,360,1032,2184};        // C-table base per source level
__constant__ int c_ck0[5]   = {0,70,140,210,282};       // l0 fine-chunk channel bounds
__constant__ int c_ck1[3]   = {192,237,282};            // l1 fine-chunk channel bounds

// dft job table: 42 jobs
__constant__ int jb_l[42]  = {0,0,0,0,0,0, 1,1,1,1,1,1, 2,2,2,2,2,2,2,2,2,2,2,2,
                              3,3,3,3,3,3,3,3,3,3,3,3, 4,4,4,4,4,4};
__constant__ int jb_c0[42] = {0,32,64,96,128,160, 0,8,16,24,32,40,
                              0,2,4,6,8,10,12,14,16,18,20,22,
                              0,1,2,3,4,5,6,7,8,9,10,11, 0,1,2,3,4,5};
__constant__ int jb_n[42]  = {32,32,32,32,32,32, 8,8,8,8,8,8, 2,2,2,2,2,2,2,2,2,2,2,2,
                              1,1,1,1,1,1,1,1,1,1,1,1, 1,1,1,1,1,1};

// scratch (device globals; no allocation)
__device__ float  d_A [NM*CT2];                        // A[m][d][c] = L[m,c,d]-L[m,d,c]
__device__ __align__(16) float d_At[NM*CT*CTP];        // At[m][c][d] (stride CTP)
__device__ float  d_Spyr[NM*1364];                     // alias pyramid of s per mode
__device__ __align__(16) float2 d_Zh[NB*12288];        // per-level DFTs of z
__device__ __align__(16) float  d_V [(size_t)NB*33*KTOT]; // Gram rows (0..31 = U-hat, 32 = w-hat)
__device__ float  d_G [NB*1089];                       // Gram accumulators (atomic)

struct InPtrs { const float* z[5]; const float* w[5]; };

// ----------------------------------------------------------- f32x2 helpers
__device__ __forceinline__ unsigned long long pack2(float a){
    unsigned long long r;
    asm("mov.b64 %0, {%1, %1};" : "=l"(r) : "f"(a));
    return r;
}
__device__ __forceinline__ void ffma2(unsigned long long &d, unsigned long long a, unsigned long long b){
    asm("fma.rn.f32x2 %0, %1, %2, %0;" : "+l"(d) : "l"(a), "l"(b));
}
__device__ __forceinline__ void fadd2(unsigned long long &d, unsigned long long a){
    asm("add.rn.f32x2 %0, %1, %0;" : "+l"(d) : "l"(a));
}
__device__ __forceinline__ void fmul2(unsigned long long &d, unsigned long long a){
    asm("mul.rn.f32x2 %0, %1, %0;" : "+l"(d) : "l"(a));
}
__device__ __forceinline__ float2 unpack2(unsigned long long v){
    float2 r;
    asm("mov.b64 {%0, %1}, %2;" : "=f"(r.x), "=f"(r.y) : "l"(v));
    return r;
}

// ---------------------------------------------------------------- A = L^T - L (+transpose)
__global__ void k_prepA(const float* __restrict__ L){
    __shared__ float Ta[32][33];
    __shared__ float Tv[32][33];
    int m  = blockIdx.z;
    int c0 = blockIdx.x*32, d0 = blockIdx.y*32;
    int tx = threadIdx.x, ty = threadIdx.y;
    const float* Lm = L + (size_t)m*CT2;
    int ci = c0+ty, dj = d0+tx;
    Ta[ty][tx] = (ci<CT && dj<CT) ? Lm[ci*CT + dj] : 0.f;
    __syncthreads();
    int di = d0+ty, cj = c0+tx;
    float v = 0.f;
    if (di<CT && cj<CT){
        v = Ta[tx][ty] - Lm[di*CT + cj];
        d_A[((size_t)m*CT + di)*CT + cj] = v;
    }
    Tv[ty][tx] = v;
    __syncthreads();
    int ci2 = c0+ty, dj2 = d0+tx;
    if (ci2<CT && dj2<CT)
        d_At[((size_t)m*CT + ci2)*CTP + dj2] = Tv[tx][ty];
}

// ------------------------------------------------------- s pyramid + zero d_G
__global__ void k_spyr(const float* __restrict__ lam){
    __shared__ float sA[1024];
    __shared__ float sB[256];
    int m = blockIdx.x;
    int tid = threadIdx.x;          // 256
    int gidx = m*256 + tid;
    if (gidx < NB*1089) d_G[gidx] = 0.f;
    const float* lm = lam + m*1024;
    for (int t=tid; t<1024; t+=256){
        int p = t>>5, q = t&31;
        float v = lm[t] - lm[(((32-p)&31)<<5) + ((32-q)&31)];
        sA[t] = v;
        d_Spyr[m*1364 + 340 + t] = v;
    }
    float* src = sA; float* dst = sB;
    int hs = 32;
    for (int k=0; k<4; ++k){
        __syncthreads();
        int hn = hs>>1;
        int off = c_LO[3-k];        // 84,20,4,0
        for (int t=tid; t<hn*hn; t+=256){
            int p = t/hn, q = t-p*hn;
            float v = src[p*hs+q] + src[(p+hn)*hs+q]
                    + src[p*hs+q+hn] + src[(p+hn)*hs+q+hn];
            dst[t] = v;
            d_Spyr[m*1364 + off + t] = v;
        }
        float* tmp = src; src = dst; dst = tmp;
        hs = hn;
    }
}

// ----------------------- batched small 2D DFTs of z (and w -> V row 32)
__global__ void __launch_bounds__(256) k_dft(InPtrs P){
    __shared__ float sIn[1024];
    __shared__ float tRe[1024];
    __shared__ float tIm[1024];
    __shared__ float2 tw[32];
    int j = blockIdx.x, b = blockIdx.y, isw = blockIdx.z;
    int l = jb_l[j];
    int h = c_h[l], hm = h-1;
    int lh = 31 - __clz(h);
    int lh2 = 2*lh;
    int h2 = h*h;
    int c0 = jb_c0[j], nch = jb_n[j];
    int npts = nch*h2;
    const float* in = (isw ? P.w[l] : P.z[l]) + (size_t)(b*c_cnt[l] + c0)*h2;
    int tid = threadIdx.x;
    if (tid < h){
        float sn, cn; __sincosf(-6.283185307179586f*(float)tid/(float)h, &sn, &cn);
        tw[tid] = make_float2(cn, sn);
    }
    for (int t=tid; t<npts; t+=256) sIn[t] = in[t];
    __syncthreads();
    for (int t=tid; t<npts; t+=256){
        int ch = t>>lh2;
        int pt = t & (h2-1);
        int p = pt>>lh, x = pt&hm;
        const float* base = sIn + (ch<<lh2) + x;
        float ar=0.f, ai=0.f;
        for (int y=0; y<h; ++y){
            float2 e = tw[(p*y)&hm];
            float v = base[y<<lh];
            ar += v*e.x; ai += v*e.y;
        }
        tRe[t]=ar; tIm[t]=ai;
    }
    __syncthreads();
    float inv = 1.0f/(float)h;
    float* vrow = d_V + ((size_t)(b*33+32))*KTOT;
    for (int t=tid; t<npts; t+=256){
        int ch = t>>lh2;
        int pt = t & (h2-1);
        int p = pt>>lh, q = pt&hm;
        const float* bR = tRe + (ch<<lh2) + (p<<lh);
        const float* bI = tIm + (ch<<lh2) + (p<<lh);
        float ar=0.f, ai=0.f;
        for (int x=0; x<h; ++x){
            float2 e = tw[(q*x)&hm];
            float re = bR[x], im = bI[x];
            ar += re*e.x - im*e.y;
            ai += re*e.y + im*e.x;
        }
        int kk = c_OffC[l] + (c0<<lh2) + t;
        if (!isw){
            d_Zh[b*12288 + kk] = make_float2(ar, ai);
        } else {
            vrow[2*kk  ] =  ai*inv;
            vrow[2*kk+1] = -ar*inv;
        }
    }
}

// ---------------- 4d x 4k fine accumulation, channels [lo,hi) clipped to levels >= l
__device__ __forceinline__ void fine_acc4x(const float2* __restrict__ sXp,
                                           const float* __restrict__ Atm, int d0,
                                           int l, int k0, int lo, int hi,
                                           unsigned long long* ac){
    for (int lc=l; lc<5; ++lc){
        int cb = c_cbase[lc], ce = c_cbase[lc+1];
        int a = lo>cb?lo:cb, e = hi<ce?hi:ce;
        if (a >= e) continue;
        int ps2 = c_PS[lc] >> 1;   // stride in ulonglong2 units
        const ulonglong2* xp = (const ulonglong2*)(sXp + c_LB[lc]
                              + (size_t)c_PS[lc]*(a-cb) + c_LO[l] + k0);
        const float* ap = Atm + (size_t)a*CTP + d0;
        #pragma unroll 2
        for (int c=a; c<e; ++c){
            float4 av = __ldg((const float4*)ap);
            ulonglong2 x01 = xp[0];
            ulonglong2 x23 = xp[1];
            unsigned long long a0=pack2(av.x), a1=pack2(av.y);
            unsigned long long a2=pack2(av.z), a3=pack2(av.w);
            ffma2(ac[0],  a0, x01.x); ffma2(ac[1],  a0, x01.y);
            ffma2(ac[2],  a0, x23.x); ffma2(ac[3],  a0, x23.y);
            ffma2(ac[4],  a1, x01.x); ffma2(ac[5],  a1, x01.y);
            ffma2(ac[6],  a1, x23.x); ffma2(ac[7],  a1, x23.y);
            ffma2(ac[8],  a2, x01.x); ffma2(ac[9],  a2, x01.y);
            ffma2(ac[10], a2, x23.x); ffma2(ac[11], a2, x23.y);
            ffma2(ac[12], a3, x01.x); ffma2(ac[13], a3, x01.y);
            ffma2(ac[14], a3, x23.x); ffma2(ac[15], a3, x23.y);
            xp += ps2;
            ap += CTP;
        }
    }
}

// ====================== fused per-(b,m) vector-field kernel ======================
__global__ void __launch_bounds__(512) k_main(){
    extern __shared__ float smraw[];
    float2* sXp = (float2*)smraw;              // [SXP_N]
    float2* sC  = sXp + SXP_N;                 // [SC_N]
    float*  sS  = (float*)(sC + SC_N);         // [1364]
    float*  sU  = sS + 1364;                   // [3072] level-0/1 U accumulators
    int m = blockIdx.x, b = blockIdx.y;
    int tid = threadIdx.x;

    for (int t=tid; t<1364; t+=512) sS[t] = d_Spyr[m*1364 + t];
    for (int t=tid; t<720;  t+=512) ((float*)sC)[t] = 0.f;   // ls=0 C region (atomic)
    __syncthreads();

    const float2* Zb = d_Zh + b*12288;

    // ---- phase 1a: finest slices  sXp = S (x) Zh
    for (int f=tid; f<12288; f+=512){
        int l, rel;
        if (f<768){l=0;rel=f;} else if (f<1536){l=1;rel=f-768;}
        else if (f<3072){l=2;rel=f-1536;} else if (f<6144){l=3;rel=f-3072;}
        else {l=4;rel=f-6144;}
        int h2 = c_h[l]*c_h[l];
        int dl = rel/h2, pt = rel-dl*h2;
        float s = sS[c_LO[l]+pt];
        float2 z = Zb[f];
        sXp[c_LB[l] + c_PS[l]*dl + c_LO[l] + pt] = make_float2(s*z.x, s*z.y);
    }
    __syncthreads();

    // ---- phase 1b: alias pyramid, 4 steps
    for (int step=1; step<=4; ++step){
        for (int lc=step; lc<=4; ++lc){
            int lt = lc-step;
            int hn = c_h[lt], hsrc = hn*2, hh = hn*hn;
            int n = c_cnt[lc]*hh;
            for (int t=tid; t<n; t+=512){
                int dl = t/hh, pt = t-dl*hh;
                int p = pt/hn, q = pt-p*hn;
                float2* bch = sXp + c_LB[lc] + c_PS[lc]*dl;
                const float2* src = bch + c_LO[lt+1];
                float2 a0=src[p*hsrc+q],    a1=src[(p+hn)*hsrc+q];
                float2 a2=src[p*hsrc+q+hn], a3=src[(p+hn)*hsrc+q+hn];
                bch[c_LO[lt]+pt] = make_float2(a0.x+a1.x+a2.x+a3.x, a0.y+a1.y+a2.y+a3.y);
            }
        }
        __syncthreads();
    }

    // ---- phase 2: coarse residue table  C[ls][di][r] = sum_c A[d,c] Zh_c[r]
    for (int it=tid; it<1110; it+=512){
        int ls, di, r0, clo, chi, hh;
        float2* Cp; bool atom;
        if (it < 270){
            ls=0; di=it/3; int chunk=it-3*di;
            r0=0; clo=chunk*64; chi=clo+64; hh=4;
            Cp = sC + di*4; atom=true;
        } else if (it < 438){
            ls=1; int t2=it-270; di=t2>>2; int rt=t2&3; r0=rt*4;
            clo=0; chi=48; hh=16; Cp = sC + 360 + di*16 + r0; atom=false;
        } else if (it < 726){
            ls=2; int t2=it-438; di=t2>>4; int rt=t2&15; r0=rt*4;
            clo=0; chi=24; hh=64; Cp = sC + 1032 + di*64 + r0; atom=false;
        } else {
            ls=3; int t2=it-726; di=t2>>6; int rt=t2&63; r0=rt*4;
            clo=0; chi=12; hh=256; Cp = sC + 2184 + di*256 + r0; atom=false;
        }
        int dg = c_cbase[ls+1] + di;
        const float* Ar = d_A + ((size_t)m*CT + dg)*CT + c_cbase[ls];
        const ulonglong2* Zp = (const ulonglong2*)(Zb + c_OffC[ls] + clo*hh + r0);
        int hh2 = hh >> 1;
        unsigned long long X0=0ull, X1=0ull, X2=0ull, X3=0ull;
        #pragma unroll 2
        for (int c=clo; c<chi; ++c){
            float a = __ldg(Ar + c);
            unsigned long long ap = pack2(a);
            ulonglong2 z01 = Zp[0];
            ulonglong2 z23 = Zp[1];
            ffma2(X0, ap, z01.x); ffma2(X1, ap, z01.y);
            ffma2(X2, ap, z23.x); ffma2(X3, ap, z23.y);
            Zp += hh2;
        }
        if (atom){
            float* f = (float*)Cp;
            float2 v0=unpack2(X0), v1=unpack2(X1), v2=unpack2(X2), v3=unpack2(X3);
            atomicAdd(f+0, v0.x); atomicAdd(f+1, v0.y);
            atomicAdd(f+2, v1.x); atomicAdd(f+3, v1.y);
            atomicAdd(f+4, v2.x); atomicAdd(f+5, v2.y);
            atomicAdd(f+6, v3.x); atomicAdd(f+7, v3.y);
        } else {
            unsigned long long* Cu = (unsigned long long*)Cp;
            Cu[0]=X0; Cu[1]=X1; Cu[2]=X2; Cu[3]=X3;
        }
    }
    __syncthreads();

    // ---- phase 3a: init sU. l0 region = 0; l1 region = s * C0 lookup
    for (int t=tid; t<1536; t+=512) sU[t] = 0.f;
    for (int t=tid; t<768; t+=512){
        int d1 = t>>4, k = t&15;
        int p = k>>2, q = k&3;
        int r = (p&1)*2 + (q&1);
        float s = sS[4 + k];
        float2 cv = sC[d1*4 + r];
        sU[1536 + 2*t    ] = s*cv.x;
        sU[1536 + 2*t + 1] = s*cv.y;
    }
    __syncthreads();

    // ---- phase 3: mixing, 4d x 4k tiles, cost-descending item order:
    // [0,192)    l0: 48 dg x 4 chunks (~71 iters)   atomic -> sU
    // [192,288)  l1: 12 dg x 4 kt x 2 chunks (~45)  atomic -> sU
    // [288,384)  l2: 6 dg x 16 kt (42)              direct
    // [384,576)  l3: 3 dg x 64 kt (18)              direct
    // [576,1088) l4: 2 dg x 256 kt (6+coarse)       direct
    float* vbase = d_V + ((size_t)(b*33+m))*KTOT;
    const float* Atm = d_At + (size_t)m*CT*CTP;
    for (int rr=0; rr<3; ++rr){
        int it;
        if (rr < 2) it = rr*512 + tid;
        else { if (tid < 448) break; it = 1024 + (511 - tid); }
        if (it >= 1088) continue;

        unsigned long long ac[16];
        #pragma unroll
        for (int j=0;j<16;++j) ac[j]=0ull;

        int l, dg, kt=0, chunk=0;
        if (it < 192){ l=0; dg=it>>2; chunk=it&3; }
        else if (it < 288){ int t2=it-192; l=1; dg=t2>>3; kt=(t2>>1)&3; chunk=t2&1; }
        else if (it < 384){ int t2=it-288; l=2; dg=t2>>4; kt=t2&15; }
        else if (it < 576){ int t2=it-384; l=3; dg=t2>>6; kt=t2&63; }
        else { int t2=it-576; l=4; dg=t2>>8; kt=t2&255; }

        int h=c_h[l], h2=h*h, hm=h-1;
        int lh = 31 - __clz(h);
        int k0 = kt*4;
        int d0 = c_cbase[l] + 4*dg;

        if (l <= 1){
            int lo = (l==0) ? c_ck0[chunk]   : c_ck1[chunk];
            int hi = (l==0) ? c_ck0[chunk+1] : c_ck1[chunk+1];
            fine_acc4x(sXp, Atm, d0, l, k0, lo, hi, ac);
            float* u = (l==0) ? (sU + d0*8)
                              : (sU + 1536 + (d0-192)*32 + k0*2);
            int dstride = (l==0) ? 8 : 32;
            #pragma unroll
            for (int dj=0;dj<4;++dj){
                #pragma unroll
                for (int kj=0;kj<4;++kj){
                    float2 v = unpack2(ac[dj*4+kj]);
                    atomicAdd(u + dj*dstride + kj*2,     v.x);
                    atomicAdd(u + dj*dstride + kj*2 + 1, v.y);
                }
            }
        } else {
            // coarse init via C table (f32x2 adds), then scale by s, then fine
            int pp[4], qq[4];
            #pragma unroll
            for (int j=0;j<4;++j){ int k=k0+j; pp[j]=k>>lh; qq[j]=k&hm; }
            for (int ls=0; ls<l; ++ls){
                int hs=c_h[ls], hh=hs*hs, hsm=hs-1;
                const unsigned long long* Cu =
                    (const unsigned long long*)(sC + c_Cb[ls] + (d0 - c_cbase[ls+1])*hh);
                #pragma unroll
                for (int j=0;j<4;++j){
                    int r = (pp[j]&hsm)*hs + (qq[j]&hsm);
                    fadd2(ac[0*4+j], Cu[r]);
                    fadd2(ac[1*4+j], Cu[hh+r]);
                    fadd2(ac[2*4+j], Cu[2*hh+r]);
                    fadd2(ac[3*4+j], Cu[3*hh+r]);
                }
            }
            const float* Sl = sS + c_LO[l] + k0;
            #pragma unroll
            for (int j=0;j<4;++j){
                unsigned long long s2 = pack2(Sl[j]);
                fmul2(ac[0*4+j], s2); fmul2(ac[1*4+j], s2);
                fmul2(ac[2*4+j], s2); fmul2(ac[3*4+j], s2);
            }

            fine_acc4x(sXp, Atm, d0, l, k0, c_cbase[l], 282, ac);

            float scale = (float)h * (1.0f/1024.0f);
            int dcnt = c_cbase[l+1] - d0; if (dcnt > 4) dcnt = 4;
            #pragma unroll
            for (int dj=0; dj<4; ++dj){
                if (dj < dcnt){
                    float* vp = vbase + 2*(c_OffC[l] + (d0 - c_cbase[l] + dj)*h2 + k0);
                    float2 u0 = unpack2(ac[dj*4+0]);
                    float2 u1 = unpack2(ac[dj*4+1]);
                    float2 u2 = unpack2(ac[dj*4+2]);
                    float2 u3 = unpack2(ac[dj*4+3]);
                    float4 o0 = make_float4(scale*u0.x, scale*u0.y, scale*u1.x, scale*u1.y);
                    float4 o1 = make_float4(scale*u2.x, scale*u2.y, scale*u3.x, scale*u3.y);
                    *(float4*)(vp)   = o0;
                    *(float4*)(vp+4) = o1;
                }
            }
        }
    }
    __syncthreads();

    // ---- phase 3d: write out levels 0-1 from sU (contiguous, matches d_V layout)
    for (int t=tid; t<3072; t+=512){
        float sc = (t<1536) ? (2.0f/1024.0f) : (4.0f/1024.0f);
        vbase[t] = sc * sU[t];
    }
}

// ------------------------------------------------- segmented 33x33 Gram -> atomic d_G
__global__ void __launch_bounds__(256) k_gram(){
    __shared__ float sm[34*257];
    int seg = blockIdx.x, b = blockIdx.y;
    int tid = threadIdx.x;          // 256
    const float* Vb = d_V + (size_t)b*33*KTOT + seg*SEG;
    for (int r=0; r<33; ++r) sm[r*257+tid] = Vb[(size_t)r*KTOT + tid];
    sm[33*257+tid] = 0.f;
    __syncthreads();
    float* gG = d_G + b*1089;
    if (tid < 153){
        int t = tid;
        int ti = (int)((35.0f - sqrtf(1225.0f - 8.0f*(float)t)) * 0.5f);
        if (ti > 16) ti = 16; if (ti < 0) ti = 0;
        int off = 17*ti - (ti*(ti-1))/2;
        while (off > t){ ti--; off = 17*ti - (ti*(ti-1))/2; }
        while (off + (17-ti) <= t){ off += 17-ti; ti++; }
        int tj = ti + (t - off);
        const float* r0 = sm + (2*ti)*257;
        const float* r1 = r0 + 257;
        const float* q0 = sm + (2*tj)*257;
        const float* q1 = q0 + 257;
        float a00=0,a01=0,a10=0,a11=0;
        #pragma unroll 4
        for (int k=0; k<SEG; ++k){
            float x0=r0[k], x1=r1[k], y0=q0[k], y1=q1[k];
            a00 += x0*y0; a01 += x0*y1;
            a10 += x1*y0; a11 += x1*y1;
        }
        int i0=2*ti, j0=2*tj;
        int i1=i0+1, j1=j0+1;
        atomicAdd(gG + i0*33+j0, a00);
        if (j1<33) atomicAdd(gG + i0*33+j1, a01);
        if (i1<33) atomicAdd(gG + i1*33+j0, a10);
        if (i1<33 && j1<33) atomicAdd(gG + i1*33+j1, a11);
        if (ti != tj){
            atomicAdd(gG + j0*33+i0, a00);
            if (j1<33) atomicAdd(gG + j1*33+i0, a01);
            if (i1<33) atomicAdd(gG + j0*33+i1, a10);
            if (i1<33 && j1<33) atomicAdd(gG + j1*33+i1, a11);
        }
    }
}

// ------------------------------------------------- stats + Cholesky + logdet
__global__ void k_final(float* __restrict__ out){
    __shared__ float G[1089];
    __shared__ float Mch[32][33];
    __shared__ float sc0;
    int b = blockIdx.x;
    int tid = threadIdx.x;          // 256
    for (int pair=tid; pair<1089; pair+=256) G[pair] = d_G[b*1089 + pair];
    __syncthreads();
    if (tid < 32){
        float dg = G[tid*33+tid];
        for (int o=16;o>0;o>>=1) dg += __shfl_down_sync(0xffffffffu, dg, o);
        if (tid==0){
            float var = dg * (1.0f/32.0f);
            if (var < 1e-6f) var = 1e-6f;
            sc0 = var;
        }
    }
    __syncthreads();
    float var = sc0;
    float inv_var = 1.0f/var;
    for (int t=tid; t<1024; t+=256){
        int i = t>>5, j = t&31;
        Mch[i][j] = G[i*33+j]*inv_var + ((i==j)?EPSR:0.f);
    }
    __syncthreads();
    for (int k=0; k<32; ++k){
        if (tid==0) Mch[k][k] = sqrtf(Mch[k][k]);
        __syncthreads();
        if (tid>k && tid<32) Mch[tid][k] /= Mch[k][k];
        __syncthreads();
        if (tid>k && tid<32){
            float lik = Mch[tid][k];
            for (int j=k+1; j<=tid; ++j) Mch[tid][j] -= lik*Mch[j][k];
        }
        __syncthreads();
    }
    if (tid < 32){
        float ld  = 2.0f*logf(Mch[tid][tid]);
        float zw  = G[tid*33+32];
        float zw2 = zw*zw;
        for (int o=16;o>0;o>>=1){
            ld  += __shfl_down_sync(0xffffffffu, ld,  o);
            zw2 += __shfl_down_sync(0xffffffffu, zw2, o);
        }
        if (tid==0){
            float trace = EPSR*G[32*33+32] + zw2*inv_var;
            out[b] = 0.5f*(ld - trace);
        }
    }
}

// ----------------------------------------------------------------------------
extern "C" void kernel_launch(void* const* d_in, const int* in_sizes, int n_in,
                              void* d_out, int out_size){
    (void)n_in; (void)out_size;
    InPtrs P;
    const float* L; const float* lam;
    if (in_sizes[0] > 1000000){
        // alphabetical: L, lam, w0..w4, z0..z4
        L   = (const float*)d_in[0];
        lam = (const float*)d_in[1];
        for (int l=0;l<5;++l){ P.w[l] = (const float*)d_in[2+l]; P.z[l] = (const float*)d_in[7+l]; }
    } else if (in_sizes[2] == 6144){
        // grouped: z0..z4, w0..w4, L, lam
        for (int l=0;l<5;++l){ P.z[l] = (const float*)d_in[l]; P.w[l] = (const float*)d_in[5+l]; }
        L   = (const float*)d_in[10];
        lam = (const float*)d_in[11];
    } else {
        // dict insertion order: z0,w0,z1,w1,...,L,lam
        for (int l=0;l<5;++l){ P.z[l] = (const float*)d_in[2*l]; P.w[l] = (const float*)d_in[2*l+1]; }
        L   = (const float*)d_in[10];
        lam = (const float*)d_in[11];
    }
    float* out = (float*)d_out;

    static int smem_set = 0;
    if (!smem_set){
        cudaFuncSetAttribute(k_main, cudaFuncAttributeMaxDynamicSharedMemorySize, SMEM_MAIN);
        smem_set = 1;
    }

    dim3 tA(32,32), gA(9,9,NM);
    k_prepA<<<gA, tA>>>(L);
    k_spyr<<<NM, 256>>>(lam);
    k_dft<<<dim3(42, NB, 2), 256>>>(P);
    k_main<<<dim3(NM, NB), 512, SMEM_MAIN>>>();
    k_gram<<<dim3(NSEG, NB), 256>>>();
    k_final<<<NB, 256>>>(out);
}